// round 5
// baseline (speedup 1.0000x reference)
#include <cuda_runtime.h>
#include <cuda_fp16.h>
#include <cstdint>

#define N_NODES 40000
#define N_EDGES 640000
#define D_FEAT  128

// ---------------------------------------------------------------------------
// Scratch (allocation-free: __device__ globals)
// ---------------------------------------------------------------------------
__device__ uint4 g_fh4[N_NODES * D_FEAT / 8];   // fp16 copy of feats (10.2 MB), 16B rows x 16
__device__ int   g_count[N_NODES];              // in-degree histogram
__device__ int   g_start[N_NODES + 1];          // CSR offsets (exclusive scan)
__device__ int   g_cursor[N_NODES];             // scatter cursors
__device__ int   g_ssrc[N_EDGES];               // src node id, dst-sorted order
__device__ int   g_seid[N_EDGES];               // original edge id, dst-sorted order
__device__ float g_ee[N_EDGES];                 // exp(e) staging, dst-sorted order

// ---------------------------------------------------------------------------
// K1: convert feats fp32 -> fp16 (16B stores) + zero histogram counters.
// Thread i handles 8 floats.
// ---------------------------------------------------------------------------
__global__ __launch_bounds__(256) void convert_kernel(const float4* __restrict__ feats4) {
    int i = blockIdx.x * blockDim.x + threadIdx.x;   // [0, 640000)
    if (i < N_NODES * D_FEAT / 8) {
        float4 v0 = feats4[2 * i];
        float4 v1 = feats4[2 * i + 1];
        __half2 h[4];
        h[0] = __floats2half2_rn(v0.x, v0.y);
        h[1] = __floats2half2_rn(v0.z, v0.w);
        h[2] = __floats2half2_rn(v1.x, v1.y);
        h[3] = __floats2half2_rn(v1.z, v1.w);
        g_fh4[i] = *(const uint4*)h;
    }
    if (i < N_NODES) g_count[i] = 0;
}

// ---------------------------------------------------------------------------
// K2: in-degree histogram
// ---------------------------------------------------------------------------
__global__ __launch_bounds__(256) void hist_kernel(const int* __restrict__ dst) {
    int i = blockIdx.x * blockDim.x + threadIdx.x;
    if (i < N_EDGES) atomicAdd(&g_count[dst[i]], 1);
}

// ---------------------------------------------------------------------------
// K3: single-block exclusive scan of g_count -> g_start, g_cursor.
// 1024 threads x 40 elements each (40960 >= 40000).
// ---------------------------------------------------------------------------
__global__ __launch_bounds__(1024) void scan_kernel() {
    const int PER = 40;
    int t = threadIdx.x;
    int base = t * PER;

    int local[PER];
    int sum = 0;
#pragma unroll
    for (int j = 0; j < PER; j++) {
        int idx = base + j;
        int c = (idx < N_NODES) ? g_count[idx] : 0;
        local[j] = sum;
        sum += c;
    }

    __shared__ int sm[1024];
    sm[t] = sum;
    __syncthreads();
    // Hillis-Steele inclusive scan over per-thread sums
    for (int d = 1; d < 1024; d <<= 1) {
        int v = (t >= d) ? sm[t - d] : 0;
        __syncthreads();
        sm[t] += v;
        __syncthreads();
    }
    int excl = (t == 0) ? 0 : sm[t - 1];

#pragma unroll
    for (int j = 0; j < PER; j++) {
        int idx = base + j;
        if (idx < N_NODES) {
            int st = excl + local[j];
            g_start[idx]  = st;
            g_cursor[idx] = st;
        }
    }
    if (t == 1023) g_start[N_NODES] = sm[1023];   // == N_EDGES
}

// ---------------------------------------------------------------------------
// K4: scatter edges into dst-sorted order
// ---------------------------------------------------------------------------
__global__ __launch_bounds__(256) void scatter_kernel(const int* __restrict__ src,
                                                      const int* __restrict__ dst) {
    int i = blockIdx.x * blockDim.x + threadIdx.x;
    if (i < N_EDGES) {
        int d = dst[i];
        int p = atomicAdd(&g_cursor[d], 1);
        g_ssrc[p] = src[i];
        g_seid[p] = i;
    }
}

// ---------------------------------------------------------------------------
// K5: warp per dst node. Load dst row once (uint2/lane = 256B/warp), loop over
// in-edges in batches of 4 (MLP), compute ee = exp(exp(-0.01*L1)), accumulate
// local sum s (no atomics!), stage ee, then write out[orig_id] = ee / s.
// ---------------------------------------------------------------------------
__global__ __launch_bounds__(256) void node_kernel(float* __restrict__ out) {
    int w    = (blockIdx.x * blockDim.x + threadIdx.x) >> 5;
    int lane = threadIdx.x & 31;
    if (w >= N_NODES) return;

    int beg = g_start[w];
    int end = g_start[w + 1];
    if (beg == end) return;

    const uint2* fh = (const uint2*)g_fh4;          // row = 32 x uint2
    uint2 br = fh[w * 32 + lane];
    __half2 b0 = *(const __half2*)&br.x;
    __half2 b1 = *(const __half2*)&br.y;

    float s = 0.0f;
    for (int i = beg; i < end; i += 4) {
        int n = end - i; if (n > 4) n = 4;

        uint2 ar[4];
#pragma unroll
        for (int j = 0; j < 4; j++) {
            int sj = g_ssrc[(j < n) ? (i + j) : i];  // broadcast load
            ar[j] = fh[sj * 32 + lane];
        }

        float ev[4];
#pragma unroll
        for (int j = 0; j < 4; j++) {
            __half2 a0 = *(const __half2*)&ar[j].x;
            __half2 a1 = *(const __half2*)&ar[j].y;
            __half2 d0 = __habs2(__hsub2(a0, b0));
            __half2 d1 = __habs2(__hsub2(a1, b1));
            float2 f0 = __half22float2(d0);
            float2 f1 = __half22float2(d1);
            float t = (f0.x + f0.y) + (f1.x + f1.y);
            t += __shfl_xor_sync(0xffffffffu, t, 16);
            t += __shfl_xor_sync(0xffffffffu, t, 8);
            t += __shfl_xor_sync(0xffffffffu, t, 4);
            t += __shfl_xor_sync(0xffffffffu, t, 2);
            t += __shfl_xor_sync(0xffffffffu, t, 1);   // all lanes hold total
            ev[j] = __expf(__expf(-0.01f * t));        // ee = exp(e)
        }

#pragma unroll
        for (int j = 0; j < 4; j++) {
            if (j < n) {
                s += ev[j];                             // same value in all lanes
                if (lane == j) g_ee[i + j] = ev[j];     // lane j stages edge i+j
            }
        }
    }

    // make staged ee visible across lanes of this warp
    __syncwarp();
    __threadfence_block();

    for (int i = beg + lane; i < end; i += 32)
        out[g_seid[i]] = __fdividef(g_ee[i], s);
}

// ---------------------------------------------------------------------------
extern "C" void kernel_launch(void* const* d_in, const int* in_sizes, int n_in,
                              void* d_out, int out_size) {
    const float4* feats4 = (const float4*)d_in[0];
    const int*    src    = (const int*)d_in[1];
    const int*    dst    = (const int*)d_in[2];
    float*        out    = (float*)d_out;

    convert_kernel<<<(N_NODES * D_FEAT / 8 + 255) / 256, 256>>>(feats4);
    hist_kernel<<<(N_EDGES + 255) / 256, 256>>>(dst);
    scan_kernel<<<1, 1024>>>();
    scatter_kernel<<<(N_EDGES + 255) / 256, 256>>>(src, dst);
    node_kernel<<<(N_NODES * 32 + 255) / 256, 256>>>(out);
}

// round 7
// speedup vs baseline: 3.4471x; 3.4471x over previous
#include <cuda_runtime.h>
#include <cuda_fp16.h>
#include <cstdint>

#define N_NODES 40000
#define N_EDGES 640000
#define D_FEAT  128

// ---------------------------------------------------------------------------
// Scratch (allocation-free: __device__ globals)
// ---------------------------------------------------------------------------
__device__ uint4              g_fh4[N_NODES * D_FEAT / 8]; // fp16 feats copy (10.2 MB)
__device__ float              g_ee[N_EDGES];               // exp(e) per edge
__device__ unsigned long long g_sum[N_NODES];              // fixed-point (2^32) segment sums

// ---------------------------------------------------------------------------
// K1: convert feats fp32 -> fp16 + zero g_sum. Each thread converts 16 floats
// as 2 independent 8-float chunks (4 outstanding LDG.128 -> latency hiding).
// ---------------------------------------------------------------------------
__global__ __launch_bounds__(256) void convert_kernel(const float4* __restrict__ feats4) {
    int i = blockIdx.x * blockDim.x + threadIdx.x;       // [0, 320000)
    const int HALF = N_NODES * D_FEAT / 16;              // 320000 uint4-outputs per half

#pragma unroll
    for (int k = 0; k < 2; k++) {
        int idx = i + k * HALF;                          // output uint4 index
        float4 v0 = feats4[2 * idx];
        float4 v1 = feats4[2 * idx + 1];
        __half2 h[4];
        h[0] = __floats2half2_rn(v0.x, v0.y);
        h[1] = __floats2half2_rn(v0.z, v0.w);
        h[2] = __floats2half2_rn(v1.x, v1.y);
        h[3] = __floats2half2_rn(v1.z, v1.w);
        g_fh4[idx] = *(const uint4*)h;
    }
    if (i < N_NODES) g_sum[i] = 0ULL;
}

// ---------------------------------------------------------------------------
// K2: 8 lanes per edge (4 edges per warp).
//   Row = 256 B = 16 x uint4. Lane l loads uint4 #l and #(l+8) of both rows:
//   4 independent LDG.128 per thread (front-batched), two contiguous 128 B
//   segments per row -> fully coalesced.
//   L1 distance: fp16 sub/abs, fp32 accumulate, 3-step shfl over the 8-group.
//     e  = exp(-0.01 * L1)  in (0, 1]
//     ee = exp(e)           in (1, 2.72]  (segment-max pass unnecessary)
//   Group leader stores ee and adds fixed-point ee to g_sum[dst] (u64 atomics
//   are associative -> deterministic).
// ---------------------------------------------------------------------------
__device__ __forceinline__ float l1_16h(uint4 a, uint4 b) {
    const __half2* ah = (const __half2*)&a;
    const __half2* bh = (const __half2*)&b;
    float acc = 0.0f;
#pragma unroll
    for (int j = 0; j < 4; j++) {
        __half2 d = __habs2(__hsub2(ah[j], bh[j]));
        float2 f = __half22float2(d);
        acc += f.x + f.y;
    }
    return acc;
}

__global__ __launch_bounds__(256) void edge_kernel(const int* __restrict__ src,
                                                   const int* __restrict__ dst) {
    int t    = blockIdx.x * blockDim.x + threadIdx.x;
    int edge = t >> 3;
    int lane = t & 7;
    if (edge >= N_EDGES) return;

    int s = src[edge];                      // broadcast within 8-group
    int d = dst[edge];

    const uint4* __restrict__ fh = g_fh4;
    uint4 a0 = fh[s * 16 + lane];
    uint4 a1 = fh[s * 16 + 8 + lane];
    uint4 b0 = fh[d * 16 + lane];
    uint4 b1 = fh[d * 16 + 8 + lane];

    float acc = l1_16h(a0, b0) + l1_16h(a1, b1);

    acc += __shfl_xor_sync(0xffffffffu, acc, 4);
    acc += __shfl_xor_sync(0xffffffffu, acc, 2);
    acc += __shfl_xor_sync(0xffffffffu, acc, 1);

    if (lane == 0) {
        float e  = __expf(-0.01f * acc);
        float ee = __expf(e);
        g_ee[edge] = ee;
        unsigned long long q = (unsigned long long)(ee * 4294967296.0f);
        atomicAdd(&g_sum[d], q);
    }
}

// ---------------------------------------------------------------------------
// K3: out[i] = ee[i] / sum[dst[i]]
// ---------------------------------------------------------------------------
__global__ __launch_bounds__(256) void finalize_kernel(const int* __restrict__ dst,
                                                       float* __restrict__ out) {
    int i = blockIdx.x * blockDim.x + threadIdx.x;
    if (i < N_EDGES) {
        float s = (float)g_sum[dst[i]] * 0x1p-32f;
        out[i] = __fdividef(g_ee[i], s);
    }
}

// ---------------------------------------------------------------------------
extern "C" void kernel_launch(void* const* d_in, const int* in_sizes, int n_in,
                              void* d_out, int out_size) {
    const float4* feats4 = (const float4*)d_in[0];
    const int*    src    = (const int*)d_in[1];
    const int*    dst    = (const int*)d_in[2];
    float*        out    = (float*)d_out;

    // 320000 threads, each converts 16 floats
    convert_kernel<<<(N_NODES * D_FEAT / 16 + 255) / 256, 256>>>(feats4);

    // 8 lanes per edge: 640000 * 8 = 5.12M threads
    edge_kernel<<<(N_EDGES * 8) / 256, 256>>>(src, dst);

    finalize_kernel<<<(N_EDGES + 255) / 256, 256>>>(dst, out);
}